// round 11
// baseline (speedup 1.0000x reference)
#include <cuda_runtime.h>
#include <cuda_fp16.h>
#include <cstdint>

#define BBATCH 2
#define HH 64
#define WW 64
#define CC 192
#define NH 6
#define HD 32
#define KW 7
#define RR 13
#define NPIX (BBATCH*HH*WW)

// scratch (device globals: allocation-free)
__device__ __half g_qkvh[(size_t)NPIX * 3 * CC];   // qkv (half, q pre-scaled)
__device__ float  g_att [(size_t)NPIX * CC];       // attention output (fp32)

__device__ __forceinline__ uint32_t smem_u32(const void* p) {
    uint32_t a;
    asm("{ .reg .u64 t; cvta.to.shared.u64 t, %1; cvt.u32.u64 %0, t; }"
        : "=r"(a) : "l"(p));
    return a;
}
__device__ __forceinline__ void cp16(uint32_t dst, const void* src) {
    asm volatile("cp.async.cg.shared.global [%0], [%1], 16;"
                 :: "r"(dst), "l"(src));
}
#define CP_COMMIT() asm volatile("cp.async.commit_group;" ::: "memory")
template<int N> __device__ __forceinline__ void cp_wait() {
    asm volatile("cp.async.wait_group %0;" :: "n"(N) : "memory");
}

// pack float2 -> half2 reg (RN), 1 cvt inst
__device__ __forceinline__ uint32_t packh2(float2 f) {
    uint32_t r;
    asm("cvt.rn.f16x2.f32 %0, %1, %2;" : "=r"(r) : "f"(f.y), "f"(f.x));
    return r;
}

__device__ __forceinline__ void mma_f16(float c[4], const uint32_t a[4],
                                        const uint32_t b[2]) {
    asm volatile(
        "mma.sync.aligned.m16n8k16.row.col.f32.f16.f16.f32 "
        "{%0,%1,%2,%3}, {%4,%5,%6,%7}, {%8,%9}, {%0,%1,%2,%3};"
        : "+f"(c[0]), "+f"(c[1]), "+f"(c[2]), "+f"(c[3])
        : "r"(a[0]), "r"(a[1]), "r"(a[2]), "r"(a[3]), "r"(b[0]), "r"(b[1]));
}

// ---------------------------------------------------------------------------
// fp32-input GEMM via fp16 mma m16n8k16 (fp32 accum), 2-stage cp.async.
// C[M,N] = A[M,192] * W[N,192]^T ; A,W fp32 row-major; converted to half
// at fragment load (cvt.rn.f16x2.f32), so numerics == pre-rounded fp16.
// K-chunk 32 floats (128B rows, 8x16B units, XOR swizzle u^=(r&7)).
// QKV: BM64 BN192 256thr (2x4 warps) -> half out (q scaled).
// Proj: BM64 BN64 128thr (2x2 warps) -> fp32 out.
// ---------------------------------------------------------------------------
#define GKD 192
#define GBKF 32                 // chunk: 32 floats
#define NCH (GKD / GBKF)        // 6

template<int BM, int BN, int THREADS, int WN, int MINB, bool HALF_OUT>
__global__ void __launch_bounds__(THREADS, MINB)
gemm32(const float* __restrict__ A, const float* __restrict__ W,
       void* __restrict__ Cout, int Ncols, int scaleQ)
{
    constexpr int NT = BN / WN / 8;          // n mma-tiles per warp
    constexpr int AU = BM * 8 / THREADS;     // A 16B-units per thread per chunk
    constexpr int BU = BN * 8 / THREADS;

    extern __shared__ float smf[];
    float* Asb = smf;                        // [2][BM][32 floats]
    float* Bsb = smf + 2 * BM * GBKF;        // [2][BN][32 floats]

    const int t    = threadIdx.x;
    const int wid  = t >> 5, lane = t & 31;
    const int g    = lane >> 2, q4 = lane & 3;
    const int wM   = wid / WN, wN = wid % WN;
    const int bm   = blockIdx.y * BM;
    const int bn   = blockIdx.x * BN;

    uint32_t a_dst[2][AU], b_dst[2][BU];
    const float* a_src[AU];
    const float* b_src[BU];
    #pragma unroll
    for (int i = 0; i < AU; i++) {
        const int u = t + i * THREADS, r = u >> 3, c = u & 7;
        a_src[i] = A + (size_t)(bm + r) * GKD + c * 4;
        #pragma unroll
        for (int bf = 0; bf < 2; bf++)
            a_dst[bf][i] = smem_u32(&Asb[(bf * BM + r) * GBKF + (c ^ (r & 7)) * 4]);
    }
    #pragma unroll
    for (int i = 0; i < BU; i++) {
        const int u = t + i * THREADS, r = u >> 3, c = u & 7;
        b_src[i] = W + (size_t)(bn + r) * GKD + c * 4;
        #pragma unroll
        for (int bf = 0; bf < 2; bf++)
            b_dst[bf][i] = smem_u32(&Bsb[(bf * BN + r) * GBKF + (c ^ (r & 7)) * 4]);
    }

    // prologue: chunks 0,1 -> bufs 0,1
    #pragma unroll
    for (int s = 0; s < 2; s++) {
        #pragma unroll
        for (int i = 0; i < AU; i++) cp16(a_dst[s][i], a_src[i] + s * GBKF);
        #pragma unroll
        for (int i = 0; i < BU; i++) cp16(b_dst[s][i], b_src[i] + s * GBKF);
        CP_COMMIT();
    }

    float acc[2][NT][4] = {};

    // fragment float-col helpers: f0 = 16*kb + 2*q4 (+8 for the a2/b1 regs)
    const int uq = q4 >> 1;            // unit sub-index from q
    const int c0 = (2 * q4) & 3;       // float offset within 16B unit

    #pragma unroll
    for (int kc = 0; kc < NCH; kc++) {
        const int buf = kc & 1;
        if (kc == NCH - 1) cp_wait<0>(); else cp_wait<1>();
        __syncthreads();

        const float* Asl = Asb + buf * BM * GBKF;
        const float* Bsl = Bsb + buf * BN * GBKF;

        #pragma unroll
        for (int kb = 0; kb < 2; kb++) {   // 2 k16 steps per 32-float chunk
            const int u0 = 4 * kb + uq;        // logical unit of k-halfs 16kb+2q
            const int u2 = u0 + 2;             // +8 halfs
            uint32_t a[2][4], b[NT][2];
            #pragma unroll
            for (int mt = 0; mt < 2; mt++) {
                const int r = wM * 32 + mt * 16 + g;    // r & 7 == g
                const int i0 = ((u0 ^ g) * 4 + c0);
                const int i2 = ((u2 ^ g) * 4 + c0);
                a[mt][0] = packh2(*(const float2*)&Asl[r * GBKF + i0]);
                a[mt][1] = packh2(*(const float2*)&Asl[(r + 8) * GBKF + i0]);
                a[mt][2] = packh2(*(const float2*)&Asl[r * GBKF + i2]);
                a[mt][3] = packh2(*(const float2*)&Asl[(r + 8) * GBKF + i2]);
            }
            #pragma unroll
            for (int nt = 0; nt < NT; nt++) {
                const int r = wN * (8 * NT) + nt * 8 + g;   // r & 7 == g
                const int i0 = ((u0 ^ g) * 4 + c0);
                const int i2 = ((u2 ^ g) * 4 + c0);
                b[nt][0] = packh2(*(const float2*)&Bsl[r * GBKF + i0]);
                b[nt][1] = packh2(*(const float2*)&Bsl[r * GBKF + i2]);
            }
            #pragma unroll
            for (int mt = 0; mt < 2; mt++)
                #pragma unroll
                for (int nt = 0; nt < NT; nt++)
                    mma_f16(acc[mt][nt], a[mt], b[nt]);
        }
        __syncthreads();

        if (kc + 2 < NCH) {
            const int ko = (kc + 2) * GBKF;
            #pragma unroll
            for (int i = 0; i < AU; i++) cp16(a_dst[buf][i], a_src[i] + ko);
            #pragma unroll
            for (int i = 0; i < BU; i++) cp16(b_dst[buf][i], b_src[i] + ko);
            CP_COMMIT();
        }
    }

    const float qs = 0.17677669529663687f;
    #pragma unroll
    for (int mt = 0; mt < 2; mt++) {
        const int row0 = bm + wM * 32 + mt * 16 + g;
        #pragma unroll
        for (int nt = 0; nt < NT; nt++) {
            const int col = bn + wN * (8 * NT) + nt * 8 + q4 * 2;
            const float sc = (scaleQ && col < CC) ? qs : 1.0f;
            if (HALF_OUT) {
                __half* C = (__half*)Cout;
                *(__half2*)(C + (size_t)row0 * Ncols + col) =
                    __floats2half2_rn(acc[mt][nt][0] * sc, acc[mt][nt][1] * sc);
                *(__half2*)(C + (size_t)(row0 + 8) * Ncols + col) =
                    __floats2half2_rn(acc[mt][nt][2] * sc, acc[mt][nt][3] * sc);
            } else {
                float* C = (float*)Cout;
                *(float2*)(C + (size_t)row0 * Ncols + col) =
                    make_float2(acc[mt][nt][0] * sc, acc[mt][nt][1] * sc);
                *(float2*)(C + (size_t)(row0 + 8) * Ncols + col) =
                    make_float2(acc[mt][nt][2] * sc, acc[mt][nt][3] * sc);
            }
        }
    }
}

// ---------------------------------------------------------------------------
// Tiled neighborhood attention, fp16 K/V in smem, fp32 output.
// ---------------------------------------------------------------------------
#define TILE_H 4
#define TILE_W 32
#define NRR (TILE_H + KW - 1)     // 10
#define NCC (TILE_W + KW - 1)     // 38
#define NNEI (NRR * NCC)          // 380
#define SROWH 40
#define SM_BYTES (2 * NNEI * SROWH * 2 + RR * RR * 4)

__global__ __launch_bounds__(128)
void natten2(const float* __restrict__ rpb, const float* __restrict__ temp)
{
    extern __shared__ char smraw[];
    __half* sKh  = (__half*)smraw;
    __half* sVh  = sKh + NNEI * SROWH;
    float*  srpb = (float*)(sVh + NNEI * SROWH);

    const int t      = threadIdx.x;
    const int tile   = blockIdx.x;
    const int bI     = blockIdx.y;
    const int head   = blockIdx.z;
    const int tile_i = (tile >> 1) * TILE_H;
    const int tile_j = (tile & 1) * TILE_W;
    const int ti0 = min(max(tile_i - 3, 0), HH - NRR);
    const int tj0 = min(max(tile_j - 3, 0), WW - NCC);
    const int pixbase = bI * HH * WW;

    const float tn = temp[head];
    for (int idx = t; idx < RR * RR; idx += 128)
        srpb[idx] = rpb[head * RR * RR + idx] * tn;

    // stage K,V: raw 16B copies of half rows
    for (int idx = t; idx < NNEI * 4; idx += 128) {
        const int u = idx & 3, r = idx >> 2;
        const int gi = ti0 + r / NCC, gj = tj0 + r % NCC;
        const __half* base =
            g_qkvh + (size_t)(pixbase + gi * WW + gj) * (3 * CC) + CC + head * HD;
        *(uint4*)(sKh + r * SROWH + u * 8) = *(const uint4*)(base + u * 8);
        *(uint4*)(sVh + r * SROWH + u * 8) = *(const uint4*)(base + CC + u * 8);
    }

    const int i  = tile_i + (t >> 5);
    const int j  = tile_j + (t & 31);
    const int pix = pixbase + i * WW + j;
    __half2 qh[16];
    {
        const __half2* qp = (const __half2*)(g_qkvh + (size_t)pix * (3 * CC) + head * HD);
        const __half2 tn2 = __float2half2_rn(tn);
        #pragma unroll
        for (int k = 0; k < 16; k++) qh[k] = __hmul2(qp[k], tn2);
    }
    __syncthreads();

    const int si = min(max(i - 3, 0), HH - KW);
    const int sj = min(max(j - 3, 0), WW - KW);
    const int lr0 = si - ti0, lc0 = sj - tj0;
    const int ri0 = si - i + 6, rj0 = sj - j + 6;

    float s[49];
    #pragma unroll
    for (int a = 0; a < 7; a++)
        #pragma unroll
        for (int c = 0; c < 7; c++)
            s[a * 7 + c] = srpb[(ri0 + a) * RR + rj0 + c];

    #pragma unroll
    for (int a = 0; a < 7; a++) {
        const __half* kb = sKh + ((lr0 + a) * NCC + lc0) * SROWH;
        #pragma unroll
        for (int c = 0; c < 7; c++) {
            const uint4* kr = (const uint4*)(kb + c * SROWH);
            __half2 acc = __float2half2_rn(0.f);
            #pragma unroll
            for (int ch = 0; ch < 4; ch++) {
                const uint4 kv = kr[ch];
                acc = __hfma2(qh[ch * 4 + 0], *(const __half2*)&kv.x, acc);
                acc = __hfma2(qh[ch * 4 + 1], *(const __half2*)&kv.y, acc);
                acc = __hfma2(qh[ch * 4 + 2], *(const __half2*)&kv.z, acc);
                acc = __hfma2(qh[ch * 4 + 3], *(const __half2*)&kv.w, acc);
            }
            const float2 f = __half22float2(acc);
            s[a * 7 + c] += f.x + f.y;
        }
    }

    float mx = s[0];
    #pragma unroll
    for (int n = 1; n < 49; n++) mx = fmaxf(mx, s[n]);
    float l = 0.f;
    #pragma unroll
    for (int n = 0; n < 49; n++) { s[n] = __expf(s[n] - mx); l += s[n]; }
    const float inv = 1.f / l;

    float o[32];
    #pragma unroll
    for (int d = 0; d < 32; d++) o[d] = 0.f;
    #pragma unroll
    for (int a = 0; a < 7; a++) {
        const __half* vb = sVh + ((lr0 + a) * NCC + lc0) * SROWH;
        __half2 oh[16];
        #pragma unroll
        for (int k = 0; k < 16; k++) oh[k] = __float2half2_rn(0.f);
        #pragma unroll
        for (int c = 0; c < 7; c++) {
            const uint4* vr = (const uint4*)(vb + c * SROWH);
            const __half2 w2 = __float2half2_rn(s[a * 7 + c]);
            #pragma unroll
            for (int ch = 0; ch < 4; ch++) {
                const uint4 vv = vr[ch];
                oh[ch * 4 + 0] = __hfma2(w2, *(const __half2*)&vv.x, oh[ch * 4 + 0]);
                oh[ch * 4 + 1] = __hfma2(w2, *(const __half2*)&vv.y, oh[ch * 4 + 1]);
                oh[ch * 4 + 2] = __hfma2(w2, *(const __half2*)&vv.z, oh[ch * 4 + 2]);
                oh[ch * 4 + 3] = __hfma2(w2, *(const __half2*)&vv.w, oh[ch * 4 + 3]);
            }
        }
        #pragma unroll
        for (int k = 0; k < 16; k++) {
            const float2 f = __half22float2(oh[k]);
            o[k * 2] += f.x; o[k * 2 + 1] += f.y;
        }
    }

    // fp32 store (proj converts to half at fragment load — same rounding)
    float4* op = (float4*)(g_att + (size_t)pix * CC + head * HD);
    #pragma unroll
    for (int d4 = 0; d4 < 8; d4++)
        op[d4] = make_float4(o[d4 * 4 + 0] * inv, o[d4 * 4 + 1] * inv,
                             o[d4 * 4 + 2] * inv, o[d4 * 4 + 3] * inv);
}

// ---------------------------------------------------------------------------
extern "C" void kernel_launch(void* const* d_in, const int* in_sizes, int n_in,
                              void* d_out, int out_size)
{
    const float* x      = (const float*)d_in[0];
    const float* w_qkv  = (const float*)d_in[1];
    const float* rpb    = (const float*)d_in[2];
    const float* temp   = (const float*)d_in[3];
    const float* w_proj = (const float*)d_in[4];
    float* out = (float*)d_out;

    void *qkvh, *attp;
    cudaGetSymbolAddress(&qkvh, g_qkvh);
    cudaGetSymbolAddress(&attp, g_att);

    const int smQ = 2 * (64 + 192) * GBKF * 4;   // 64 KB
    const int smP = 2 * (64 + 64) * GBKF * 4;    // 32 KB
    cudaFuncSetAttribute((void*)gemm32<64, 192, 256, 4, 2, true>,
                         cudaFuncAttributeMaxDynamicSharedMemorySize, smQ);
    cudaFuncSetAttribute((void*)gemm32<64, 64, 128, 2, 4, false>,
                         cudaFuncAttributeMaxDynamicSharedMemorySize, smP);
    cudaFuncSetAttribute(natten2, cudaFuncAttributeMaxDynamicSharedMemorySize,
                         SM_BYTES);

    // 1) QKV projection: fp32 in -> half out (q pre-scaled)
    gemm32<64, 192, 256, 4, 2, true><<<dim3(3, NPIX / 64), 256, smQ>>>(
        x, w_qkv, qkvh, 3 * CC, 1);

    // 2) tiled neighborhood attention -> g_att (fp32)
    natten2<<<dim3(32, BBATCH, NH), 128, SM_BYTES>>>(rpb, temp);

    // 3) output projection: fp32 in -> fp32 out
    gemm32<64, 64, 128, 2, 4, false><<<dim3(3, NPIX / 64), 128, smP>>>(
        (const float*)attp, w_proj, out, CC, 0);
}

// round 12
// speedup vs baseline: 1.1414x; 1.1414x over previous
#include <cuda_runtime.h>
#include <cuda_fp16.h>
#include <cstdint>

#define BBATCH 2
#define HH 64
#define WW 64
#define CC 192
#define NH 6
#define HD 32
#define KW 7
#define RR 13
#define NPIX (BBATCH*HH*WW)

// scratch (device globals: allocation-free) — all fp16
__device__ __half g_xh  [(size_t)NPIX * CC];
__device__ __half g_wqh [(size_t)3 * CC * CC];
__device__ __half g_wph [(size_t)CC * CC];
__device__ __half g_qkvh[(size_t)NPIX * 3 * CC];
__device__ __half g_atth[(size_t)NPIX * CC];

__device__ __forceinline__ uint32_t smem_u32(const void* p) {
    uint32_t a;
    asm("{ .reg .u64 t; cvta.to.shared.u64 t, %1; cvt.u32.u64 %0, t; }"
        : "=r"(a) : "l"(p));
    return a;
}
__device__ __forceinline__ void cp16(uint32_t dst, const void* src) {
    asm volatile("cp.async.cg.shared.global [%0], [%1], 16;"
                 :: "r"(dst), "l"(src));
}
#define CP_COMMIT() asm volatile("cp.async.commit_group;" ::: "memory")
template<int N> __device__ __forceinline__ void cp_wait() {
    asm volatile("cp.async.wait_group %0;" :: "n"(N) : "memory");
}

__device__ __forceinline__ void mma_f16(float c[4], const uint32_t a[4],
                                        const uint32_t b[2]) {
    asm volatile(
        "mma.sync.aligned.m16n8k16.row.col.f32.f16.f16.f32 "
        "{%0,%1,%2,%3}, {%4,%5,%6,%7}, {%8,%9}, {%0,%1,%2,%3};"
        : "+f"(c[0]), "+f"(c[1]), "+f"(c[2]), "+f"(c[3])
        : "r"(a[0]), "r"(a[1]), "r"(a[2]), "r"(a[3]), "r"(b[0]), "r"(b[1]));
}

// ---------------------------------------------------------------------------
// Pre-pass: convert x, w_qkv, w_proj fp32 -> fp16.
// ---------------------------------------------------------------------------
#define N4X ((NPIX * CC) / 4)
#define N4Q ((3 * CC * CC) / 4)
#define N4P ((CC * CC) / 4)
#define N4TOT (N4X + N4Q + N4P)

__global__ __launch_bounds__(256)
void cvt_pass(const float* __restrict__ x, const float* __restrict__ wq,
              const float* __restrict__ wp)
{
    const int idx = blockIdx.x * 256 + threadIdx.x;
    if (idx >= N4TOT) return;
    const float4* src;
    __half* dst;
    int off;
    if (idx < N4X)            { src = (const float4*)x;  dst = g_xh;  off = idx; }
    else if (idx < N4X + N4Q) { src = (const float4*)wq; dst = g_wqh; off = idx - N4X; }
    else                      { src = (const float4*)wp; dst = g_wph; off = idx - N4X - N4Q; }
    const float4 v = src[off];
    __half2* d2 = (__half2*)(dst + (size_t)off * 4);
    d2[0] = __floats2half2_rn(v.x, v.y);
    d2[1] = __floats2half2_rn(v.z, v.w);
}

// ---------------------------------------------------------------------------
// fp16 GEMM via mma.sync m16n8k16 (fp32 accum), 2-stage cp.async.
// C[M,N] = A[M,192] * W[N,192]^T, fp16 in, row-major NT.
// K-chunk 64 halfs (128B rows, 8x16B units, XOR swizzle u^=(r&7)).
// QKV: BM64 BN96 256thr (2x4 warps, warp 32x24), grid (6,128)=768 CTAs,
//      launch_bounds(256,3) -> 3 CTAs/SM -> 24 warps/SM. Half out, q scaled.
// Proj: BM32 BN96 128thr (1x4 warps, warp 32x24), grid (2,256)=512 CTAs,
//      fp32 out.
// ---------------------------------------------------------------------------
#define GKD 192
#define GBKH 64                 // chunk: 64 halfs
#define NCH (GKD / GBKH)        // 3

template<int BM, int BN, int THREADS, int WN, int MINB, bool HALF_OUT>
__global__ void __launch_bounds__(THREADS, MINB)
gemm_h(const __half* __restrict__ A, const __half* __restrict__ W,
       void* __restrict__ Cout, int Ncols, int scaleQ)
{
    constexpr int NT = BN / WN / 8;          // n mma-tiles per warp
    constexpr int AU = BM * 8 / THREADS;     // A 16B-units per thread
    constexpr int BU = BN * 8 / THREADS;     // B 16B-units per thread

    extern __shared__ uint32_t smw[];
    uint32_t* Asb = smw;                     // [2][BM][32 words]
    uint32_t* Bsb = smw + 2 * BM * 32;       // [2][BN][32 words]

    const int t    = threadIdx.x;
    const int wid  = t >> 5, lane = t & 31;
    const int g    = lane >> 2, q4 = lane & 3;
    const int wM   = wid / WN, wN = wid % WN;
    const int bm   = blockIdx.y * BM;
    const int bn   = blockIdx.x * BN;

    uint32_t a_dst[2][AU], b_dst[2][BU];
    const __half* a_src[AU];
    const __half* b_src[BU];
    #pragma unroll
    for (int i = 0; i < AU; i++) {
        const int u = t + i * THREADS, r = u >> 3, c = u & 7;
        a_src[i] = A + (size_t)(bm + r) * GKD + c * 8;
        #pragma unroll
        for (int bf = 0; bf < 2; bf++)
            a_dst[bf][i] = smem_u32(&Asb[(bf * BM + r) * 32 + (c ^ (r & 7)) * 4]);
    }
    #pragma unroll
    for (int i = 0; i < BU; i++) {
        const int u = t + i * THREADS, r = u >> 3, c = u & 7;
        b_src[i] = W + (size_t)(bn + r) * GKD + c * 8;
        #pragma unroll
        for (int bf = 0; bf < 2; bf++)
            b_dst[bf][i] = smem_u32(&Bsb[(bf * BN + r) * 32 + (c ^ (r & 7)) * 4]);
    }

    // prologue: chunks 0,1 -> bufs 0,1
    #pragma unroll
    for (int s = 0; s < 2; s++) {
        #pragma unroll
        for (int i = 0; i < AU; i++) cp16(a_dst[s][i], a_src[i] + s * GBKH);
        #pragma unroll
        for (int i = 0; i < BU; i++) cp16(b_dst[s][i], b_src[i] + s * GBKH);
        CP_COMMIT();
    }

    float acc[2][NT][4] = {};

    #pragma unroll
    for (int kc = 0; kc < NCH; kc++) {
        const int buf = kc & 1;
        if (kc == NCH - 1) cp_wait<0>(); else cp_wait<1>();
        __syncthreads();

        const uint32_t* Asl = Asb + buf * BM * 32;
        const uint32_t* Bsl = Bsb + buf * BN * 32;

        #pragma unroll
        for (int kb = 0; kb < 4; kb++) {          // 4 k16 steps per chunk
            const int w0 = ((2 * kb) ^ g) * 4 + q4;
            const int w1 = ((2 * kb + 1) ^ g) * 4 + q4;
            uint32_t a[2][4], b[NT][2];
            #pragma unroll
            for (int mt = 0; mt < 2; mt++) {
                const int r = wM * 32 + mt * 16 + g;
                a[mt][0] = Asl[r * 32 + w0];
                a[mt][1] = Asl[(r + 8) * 32 + w0];
                a[mt][2] = Asl[r * 32 + w1];
                a[mt][3] = Asl[(r + 8) * 32 + w1];
            }
            #pragma unroll
            for (int nt = 0; nt < NT; nt++) {
                const int r = wN * (8 * NT) + nt * 8 + g;
                b[nt][0] = Bsl[r * 32 + w0];
                b[nt][1] = Bsl[r * 32 + w1];
            }
            #pragma unroll
            for (int mt = 0; mt < 2; mt++)
                #pragma unroll
                for (int nt = 0; nt < NT; nt++)
                    mma_f16(acc[mt][nt], a[mt], b[nt]);
        }
        __syncthreads();

        if (kc + 2 < NCH) {
            const int ko = (kc + 2) * GBKH;
            #pragma unroll
            for (int i = 0; i < AU; i++) cp16(a_dst[buf][i], a_src[i] + ko);
            #pragma unroll
            for (int i = 0; i < BU; i++) cp16(b_dst[buf][i], b_src[i] + ko);
            CP_COMMIT();
        }
    }

    const float qs = 0.17677669529663687f;
    #pragma unroll
    for (int mt = 0; mt < 2; mt++) {
        const int row0 = bm + wM * 32 + mt * 16 + g;
        #pragma unroll
        for (int nt = 0; nt < NT; nt++) {
            const int col = bn + wN * (8 * NT) + nt * 8 + q4 * 2;
            const float sc = (scaleQ && col < CC) ? qs : 1.0f;
            if (HALF_OUT) {
                __half* C = (__half*)Cout;
                *(__half2*)(C + (size_t)row0 * Ncols + col) =
                    __floats2half2_rn(acc[mt][nt][0] * sc, acc[mt][nt][1] * sc);
                *(__half2*)(C + (size_t)(row0 + 8) * Ncols + col) =
                    __floats2half2_rn(acc[mt][nt][2] * sc, acc[mt][nt][3] * sc);
            } else {
                float* C = (float*)Cout;
                *(float2*)(C + (size_t)row0 * Ncols + col) =
                    make_float2(acc[mt][nt][0] * sc, acc[mt][nt][1] * sc);
                *(float2*)(C + (size_t)(row0 + 8) * Ncols + col) =
                    make_float2(acc[mt][nt][2] * sc, acc[mt][nt][3] * sc);
            }
        }
    }
}

// ---------------------------------------------------------------------------
// Tiled neighborhood attention, all-fp16 I/O (identical to R10).
// ---------------------------------------------------------------------------
#define TILE_H 4
#define TILE_W 32
#define NRR (TILE_H + KW - 1)     // 10
#define NCC (TILE_W + KW - 1)     // 38
#define NNEI (NRR * NCC)          // 380
#define SROWH 40
#define SM_BYTES (2 * NNEI * SROWH * 2 + RR * RR * 4)

__global__ __launch_bounds__(128)
void natten2(const float* __restrict__ rpb, const float* __restrict__ temp)
{
    extern __shared__ char smraw[];
    __half* sKh  = (__half*)smraw;
    __half* sVh  = sKh + NNEI * SROWH;
    float*  srpb = (float*)(sVh + NNEI * SROWH);

    const int t      = threadIdx.x;
    const int tile   = blockIdx.x;
    const int bI     = blockIdx.y;
    const int head   = blockIdx.z;
    const int tile_i = (tile >> 1) * TILE_H;
    const int tile_j = (tile & 1) * TILE_W;
    const int ti0 = min(max(tile_i - 3, 0), HH - NRR);
    const int tj0 = min(max(tile_j - 3, 0), WW - NCC);
    const int pixbase = bI * HH * WW;

    const float tn = temp[head];
    for (int idx = t; idx < RR * RR; idx += 128)
        srpb[idx] = rpb[head * RR * RR + idx] * tn;

    // stage K,V: raw 16B copies of half rows
    for (int idx = t; idx < NNEI * 4; idx += 128) {
        const int u = idx & 3, r = idx >> 2;
        const int gi = ti0 + r / NCC, gj = tj0 + r % NCC;
        const __half* base =
            g_qkvh + (size_t)(pixbase + gi * WW + gj) * (3 * CC) + CC + head * HD;
        *(uint4*)(sKh + r * SROWH + u * 8) = *(const uint4*)(base + u * 8);
        *(uint4*)(sVh + r * SROWH + u * 8) = *(const uint4*)(base + CC + u * 8);
    }

    const int i  = tile_i + (t >> 5);
    const int j  = tile_j + (t & 31);
    const int pix = pixbase + i * WW + j;
    __half2 qh[16];
    {
        const __half2* qp = (const __half2*)(g_qkvh + (size_t)pix * (3 * CC) + head * HD);
        const __half2 tn2 = __float2half2_rn(tn);
        #pragma unroll
        for (int k = 0; k < 16; k++) qh[k] = __hmul2(qp[k], tn2);
    }
    __syncthreads();

    const int si = min(max(i - 3, 0), HH - KW);
    const int sj = min(max(j - 3, 0), WW - KW);
    const int lr0 = si - ti0, lc0 = sj - tj0;
    const int ri0 = si - i + 6, rj0 = sj - j + 6;

    float s[49];
    #pragma unroll
    for (int a = 0; a < 7; a++)
        #pragma unroll
        for (int c = 0; c < 7; c++)
            s[a * 7 + c] = srpb[(ri0 + a) * RR + rj0 + c];

    #pragma unroll
    for (int a = 0; a < 7; a++) {
        const __half* kb = sKh + ((lr0 + a) * NCC + lc0) * SROWH;
        #pragma unroll
        for (int c = 0; c < 7; c++) {
            const uint4* kr = (const uint4*)(kb + c * SROWH);
            __half2 acc = __float2half2_rn(0.f);
            #pragma unroll
            for (int ch = 0; ch < 4; ch++) {
                const uint4 kv = kr[ch];
                acc = __hfma2(qh[ch * 4 + 0], *(const __half2*)&kv.x, acc);
                acc = __hfma2(qh[ch * 4 + 1], *(const __half2*)&kv.y, acc);
                acc = __hfma2(qh[ch * 4 + 2], *(const __half2*)&kv.z, acc);
                acc = __hfma2(qh[ch * 4 + 3], *(const __half2*)&kv.w, acc);
            }
            const float2 f = __half22float2(acc);
            s[a * 7 + c] += f.x + f.y;
        }
    }

    float mx = s[0];
    #pragma unroll
    for (int n = 1; n < 49; n++) mx = fmaxf(mx, s[n]);
    float l = 0.f;
    #pragma unroll
    for (int n = 0; n < 49; n++) { s[n] = __expf(s[n] - mx); l += s[n]; }
    const float inv = 1.f / l;

    float o[32];
    #pragma unroll
    for (int d = 0; d < 32; d++) o[d] = 0.f;
    #pragma unroll
    for (int a = 0; a < 7; a++) {
        const __half* vb = sVh + ((lr0 + a) * NCC + lc0) * SROWH;
        __half2 oh[16];
        #pragma unroll
        for (int k = 0; k < 16; k++) oh[k] = __float2half2_rn(0.f);
        #pragma unroll
        for (int c = 0; c < 7; c++) {
            const uint4* vr = (const uint4*)(vb + c * SROWH);
            const __half2 w2 = __float2half2_rn(s[a * 7 + c]);
            #pragma unroll
            for (int ch = 0; ch < 4; ch++) {
                const uint4 vv = vr[ch];
                oh[ch * 4 + 0] = __hfma2(w2, *(const __half2*)&vv.x, oh[ch * 4 + 0]);
                oh[ch * 4 + 1] = __hfma2(w2, *(const __half2*)&vv.y, oh[ch * 4 + 1]);
                oh[ch * 4 + 2] = __hfma2(w2, *(const __half2*)&vv.z, oh[ch * 4 + 2]);
                oh[ch * 4 + 3] = __hfma2(w2, *(const __half2*)&vv.w, oh[ch * 4 + 3]);
            }
        }
        #pragma unroll
        for (int k = 0; k < 16; k++) {
            const float2 f = __half22float2(oh[k]);
            o[k * 2] += f.x; o[k * 2 + 1] += f.y;
        }
    }

    // store fp16 (feeds proj GEMM)
    __half2* op = (__half2*)(g_atth + (size_t)pix * CC + head * HD);
    #pragma unroll
    for (int k = 0; k < 16; k++)
        op[k] = __floats2half2_rn(o[k * 2] * inv, o[k * 2 + 1] * inv);
}

// ---------------------------------------------------------------------------
extern "C" void kernel_launch(void* const* d_in, const int* in_sizes, int n_in,
                              void* d_out, int out_size)
{
    const float* x      = (const float*)d_in[0];
    const float* w_qkv  = (const float*)d_in[1];
    const float* rpb    = (const float*)d_in[2];
    const float* temp   = (const float*)d_in[3];
    const float* w_proj = (const float*)d_in[4];
    float* out = (float*)d_out;

    void *xh, *wqh, *wph, *qkvh, *atth;
    cudaGetSymbolAddress(&xh,   g_xh);
    cudaGetSymbolAddress(&wqh,  g_wqh);
    cudaGetSymbolAddress(&wph,  g_wph);
    cudaGetSymbolAddress(&qkvh, g_qkvh);
    cudaGetSymbolAddress(&atth, g_atth);

    const int smQ = 2 * (64 + 96) * 32 * 4;    // 40 KB
    const int smP = 2 * (32 + 96) * 32 * 4;    // 32 KB
    cudaFuncSetAttribute((void*)gemm_h<64, 96, 256, 4, 3, true>,
                         cudaFuncAttributeMaxDynamicSharedMemorySize, smQ);
    cudaFuncSetAttribute((void*)gemm_h<32, 96, 128, 4, 3, false>,
                         cudaFuncAttributeMaxDynamicSharedMemorySize, smP);
    cudaFuncSetAttribute(natten2, cudaFuncAttributeMaxDynamicSharedMemorySize,
                         SM_BYTES);

    // 0) fp32 -> fp16 conversion pre-pass
    cvt_pass<<<(N4TOT + 255) / 256, 256>>>(x, w_qkv, w_proj);

    // 1) QKV projection: [8192,192] x [576,192]^T -> g_qkvh (half, q scaled)
    gemm_h<64, 96, 256, 4, 3, true><<<dim3(6, NPIX / 64), 256, smQ>>>(
        (const __half*)xh, (const __half*)wqh, qkvh, 3 * CC, 1);

    // 2) tiled neighborhood attention -> g_atth (half)
    natten2<<<dim3(32, BBATCH, NH), 128, SM_BYTES>>>(rpb, temp);

    // 3) output projection: [8192,192] x [192,192]^T -> out (fp32)
    gemm_h<32, 96, 128, 4, 3, false><<<dim3(2, NPIX / 32), 128, smP>>>(
        (const __half*)atth, (const __half*)wph, out, CC, 0);
}